// round 6
// baseline (speedup 1.0000x reference)
#include <cuda_runtime.h>
#include <cuda_bf16.h>
#include <cuda_fp8.h>
#include <cstdint>

// Energy-distance loss, FP8 QMMA + software-pipelined job loop.
//   loss = mean_b[ mean||x-y|| - 0.5 mean||x-x'|| - 0.5 mean||y-y'|| ]
// R6: double-buffered cp.async prefetch of next job's tiles, ONE barrier
// per job, per-warp partials straight to global (no smem reduction).

#define NPTS  512
#define DIMS  128
#define NB    128
#define NROWS 65536
#define N_CROSS_CTAS 2048
#define N_SELF_CTAS  1280
#define N_JOBS (N_CROSS_CTAS + 2 * N_SELF_CTAS)   // 4608
#define JOBS_PER_CTA 16
#define N_CTAS (N_JOBS / JOBS_PER_CTA)            // 288

__device__ uint8_t g_fx[NROWS * DIMS];   // 8 MB e4m3
__device__ uint8_t g_fy[NROWS * DIMS];   // 8 MB e4m3
__device__ float g_norm_x[NROWS];
__device__ float g_norm_y[NROWS];
__device__ float g_partials[N_JOBS * 8];

// smem layout (bytes from 1024-aligned base); double-buffered
#define OFF_A    0        // A[p] at p*16384         (2 x 16 KB)
#define OFF_B    32768    // B[p] at 32768+p*16384   (2 x 16 KB)
#define OFF_NX   65536    // NX[p] at 65536+p*512
#define OFF_NY   66560    // NY[p] at 66560+p*512
#define SMEM_REQ (1024 + 67584)

__device__ __forceinline__ uint32_t smem_u32(const void* p) {
    uint32_t a;
    asm("{ .reg .u64 t; cvta.to.shared.u64 t, %1; cvt.u32.u64 %0, t; }"
        : "=r"(a) : "l"(p));
    return a;
}

struct Job {
    const uint8_t *Ab, *Bb;
    const float *nA, *nB;
    int tr, tc;
    bool selfm, diag;
};

__device__ __forceinline__ Job decode_job(int job) {
    Job J;
    int b, tr, tc;
    if (job < N_CROSS_CTAS) {
        b = job >> 4;
        int t = job & 15;
        tr = t >> 2; tc = t & 3;
        J.Ab = g_fx + ((size_t)b * NPTS + tr * 128) * DIMS;
        J.Bb = g_fy + ((size_t)b * NPTS + tc * 128) * DIMS;
        J.nA = g_norm_x + b * NPTS + tr * 128;
        J.nB = g_norm_y + b * NPTS + tc * 128;
        J.selfm = false;
    } else {
        int r = job - N_CROSS_CTAS;
        int isY = (r >= N_SELF_CTAS);
        if (isY) r -= N_SELF_CTAS;
        b = r / 10;
        int t = r - b * 10;
        int trr = 0, tt = t;
        while (tt >= 4 - trr) { tt -= 4 - trr; trr++; }
        tr = trr; tc = trr + tt;
        const uint8_t* base = isY ? g_fy : g_fx;
        const float* nbase = isY ? g_norm_y : g_norm_x;
        J.Ab = base + ((size_t)b * NPTS + tr * 128) * DIMS;
        J.Bb = base + ((size_t)b * NPTS + tc * 128) * DIMS;
        J.nA = nbase + b * NPTS + tr * 128;
        J.nB = nbase + b * NPTS + tc * 128;
        J.selfm = true;
    }
    J.tr = tr; J.tc = tc;
    J.diag = J.selfm && (tr == tc);
    return J;
}

// ---------------------------------------------------------------------------
// Kernel 0: fp32 -> e4m3 convert + exact fp32 squared norms. 8 rows/warp.
// ---------------------------------------------------------------------------
__global__ void prep_kernel(const float* __restrict__ X,
                            const float* __restrict__ Y) {
    int warp = (blockIdx.x * blockDim.x + threadIdx.x) >> 5;
    int lane = threadIdx.x & 31;
    int row8 = warp * 8;
    const float* src; uint8_t* dst; float* ndst; int r0;
    if (row8 < NROWS) { src = X; dst = g_fx; ndst = g_norm_x; r0 = row8; }
    else              { src = Y; dst = g_fy; ndst = g_norm_y; r0 = row8 - NROWS; }

    float4 v[8];
    float s[8];
#pragma unroll
    for (int k = 0; k < 8; k++) {
        v[k] = ((const float4*)(src + (size_t)(r0 + k) * DIMS))[lane];
        s[k] = v[k].x * v[k].x + v[k].y * v[k].y + v[k].z * v[k].z + v[k].w * v[k].w;
    }
#pragma unroll
    for (int k = 0; k < 8; k++) {
        float2 lo = make_float2(v[k].x, v[k].y);
        float2 hi = make_float2(v[k].z, v[k].w);
        unsigned p0 = __nv_cvt_float2_to_fp8x2(lo, __NV_SATFINITE, __NV_E4M3);
        unsigned p1 = __nv_cvt_float2_to_fp8x2(hi, __NV_SATFINITE, __NV_E4M3);
        *(unsigned*)(dst + (size_t)(r0 + k) * DIMS + lane * 4) =
            (p0 & 0xffffu) | (p1 << 16);
#pragma unroll
        for (int o = 16; o; o >>= 1) s[k] += __shfl_xor_sync(0xffffffffu, s[k], o);
        if (lane == 0) ndst[r0 + k] = s[k];
    }
}

// ---------------------------------------------------------------------------
// Kernel 1: pipelined 128x128 fp8 distance tiles.
// ---------------------------------------------------------------------------
__device__ __forceinline__ void stage_job(const Job& J, uint32_t sbase,
                                          char* /*sm*/, int p, int tid) {
    uint32_t dstA = sbase + OFF_A + p * 16384;
    uint32_t dstB = sbase + OFF_B + p * 16384;
#pragma unroll
    for (int q = 0; q < 4; q++) {
        int idx = tid + q * 256;           // 0..1023
        int r = idx >> 3, u = idx & 7;
        int soff = r * 128 + ((u ^ (r & 7)) << 4);
        asm volatile("cp.async.cg.shared.global [%0], [%1], 16;"
                     :: "r"(dstB + soff),
                        "l"((const void*)(J.Bb + (size_t)r * DIMS + u * 16)));
        asm volatile("cp.async.cg.shared.global [%0], [%1], 16;"
                     :: "r"(dstA + soff),
                        "l"((const void*)(J.Ab + (size_t)r * DIMS + u * 16)));
    }
    if (tid < 32) {
        asm volatile("cp.async.ca.shared.global [%0], [%1], 16;"
                     :: "r"(sbase + OFF_NX + p * 512 + tid * 16),
                        "l"((const void*)(J.nA + tid * 4)));
    } else if (tid < 64) {
        int t = tid - 32;
        asm volatile("cp.async.ca.shared.global [%0], [%1], 16;"
                     :: "r"(sbase + OFF_NY + p * 512 + t * 16),
                        "l"((const void*)(J.nB + t * 4)));
    }
}

__global__ __launch_bounds__(256, 2)
void dist_kernel() {
    extern __shared__ char dyn_smem[];
    char* sm = (char*)((((uintptr_t)dyn_smem) + 1023) & ~(uintptr_t)1023);
    uint32_t sbase = smem_u32(sm);

    int tid  = threadIdx.x;
    int lane = tid & 31;
    int warp = tid >> 5;
    int wm   = warp >> 1;
    int wn   = warp & 1;

    int a_r = (lane & 7) + ((lane >> 3) & 1) * 8;
    int a_u = lane >> 4;
    int b_r = (lane & 7) + ((lane >> 4) << 3);
    int b_u = (lane >> 3) & 1;

    int j0 = blockIdx.x * JOBS_PER_CTA;
    int j1 = j0 + JOBS_PER_CTA;

    // prologue: stage first job into buffer 0
    Job Jcur = decode_job(j0);
    stage_job(Jcur, sbase, sm, 0, tid);
    asm volatile("cp.async.commit_group;");

    for (int job = j0; job < j1; job++) {
        int p = (job - j0) & 1;

        // my copies for buffer p done; barrier makes it collective AND
        // proves everyone finished reading buffer p^1 (prev job's mainloop)
        asm volatile("cp.async.wait_group 0;" ::: "memory");
        __syncthreads();

        // prefetch next job into the buffer just freed
        Job Jnext;
        if (job + 1 < j1) {
            Jnext = decode_job(job + 1);
            stage_job(Jnext, sbase, sm, p ^ 1, tid);
            asm volatile("cp.async.commit_group;");
        }

        // ---- mainloop on buffer p ----
        uint32_t sA = sbase + OFF_A + p * 16384;
        uint32_t sB = sbase + OFF_B + p * 16384;

        float acc[2][8][4];
#pragma unroll
        for (int mt = 0; mt < 2; mt++)
#pragma unroll
            for (int nt = 0; nt < 8; nt++)
#pragma unroll
                for (int c = 0; c < 4; c++) acc[mt][nt][c] = 0.f;

#pragma unroll
        for (int kk = 0; kk < 4; kk++) {
            unsigned af[2][4];
#pragma unroll
            for (int mt = 0; mt < 2; mt++) {
                int r = wm * 32 + mt * 16 + a_r;
                int u = kk * 2 + a_u;
                unsigned addr = sA + (unsigned)(r * 128 + ((u ^ (r & 7)) << 4));
                asm volatile(
                    "ldmatrix.sync.aligned.m8n8.x4.shared.b16 {%0,%1,%2,%3}, [%4];"
                    : "=r"(af[mt][0]), "=r"(af[mt][1]), "=r"(af[mt][2]), "=r"(af[mt][3])
                    : "r"(addr));
            }
#pragma unroll
            for (int pp = 0; pp < 4; pp++) {
                int r = wn * 64 + pp * 16 + b_r;
                int u = kk * 2 + b_u;
                unsigned addr = sB + (unsigned)(r * 128 + ((u ^ (r & 7)) << 4));
                unsigned bf[4];
                asm volatile(
                    "ldmatrix.sync.aligned.m8n8.x4.shared.b16 {%0,%1,%2,%3}, [%4];"
                    : "=r"(bf[0]), "=r"(bf[1]), "=r"(bf[2]), "=r"(bf[3])
                    : "r"(addr));
#pragma unroll
                for (int mt = 0; mt < 2; mt++) {
                    asm volatile(
                        "mma.sync.aligned.m16n8k32.row.col.f32.e4m3.e4m3.f32 "
                        "{%0,%1,%2,%3}, {%4,%5,%6,%7}, {%8,%9}, {%0,%1,%2,%3};"
                        : "+f"(acc[mt][2*pp][0]), "+f"(acc[mt][2*pp][1]),
                          "+f"(acc[mt][2*pp][2]), "+f"(acc[mt][2*pp][3])
                        : "r"(af[mt][0]), "r"(af[mt][1]), "r"(af[mt][2]), "r"(af[mt][3]),
                          "r"(bf[0]), "r"(bf[1]));
                    asm volatile(
                        "mma.sync.aligned.m16n8k32.row.col.f32.e4m3.e4m3.f32 "
                        "{%0,%1,%2,%3}, {%4,%5,%6,%7}, {%8,%9}, {%0,%1,%2,%3};"
                        : "+f"(acc[mt][2*pp+1][0]), "+f"(acc[mt][2*pp+1][1]),
                          "+f"(acc[mt][2*pp+1][2]), "+f"(acc[mt][2*pp+1][3])
                        : "r"(af[mt][0]), "r"(af[mt][1]), "r"(af[mt][2]), "r"(af[mt][3]),
                          "r"(bf[2]), "r"(bf[3]));
                }
            }
        }

        // ---- epilogue ----
        const char* NXp = sm + OFF_NX + p * 512;
        const char* NYp = sm + OFF_NY + p * 512;
        int g  = lane >> 2;
        int ct = lane & 3;

        int   irow[2][2];
        float nx[2][2];
#pragma unroll
        for (int mt = 0; mt < 2; mt++) {
            int r0 = wm * 32 + mt * 16 + g;
            irow[mt][0] = Jcur.tr * 128 + r0;
            irow[mt][1] = irow[mt][0] + 8;
            nx[mt][0] = *(const float*)(NXp + r0 * 4);
            nx[mt][1] = *(const float*)(NXp + (r0 + 8) * 4);
        }
        int   jcol[8][2];
        float ny[8][2];
#pragma unroll
        for (int nt = 0; nt < 8; nt++) {
            int c0 = wn * 64 + nt * 8 + 2 * ct;
            jcol[nt][0] = Jcur.tc * 128 + c0;
            jcol[nt][1] = jcol[nt][0] + 1;
            ny[nt][0] = *(const float*)(NYp + c0 * 4);
            ny[nt][1] = *(const float*)(NYp + (c0 + 1) * 4);
        }

        float ts0 = 0.f, ts1 = 0.f;
        if (Jcur.diag) {
#pragma unroll
            for (int mt = 0; mt < 2; mt++)
#pragma unroll
                for (int nt = 0; nt < 8; nt++)
#pragma unroll
                    for (int c = 0; c < 4; c++) {
                        int ri = c >> 1, cj = c & 1;
                        float d2 = nx[mt][ri] + ny[nt][cj] - 2.f * acc[mt][nt][c];
                        float dd;
                        asm("sqrt.approx.f32 %0, %1;" : "=f"(dd) : "f"(d2));
                        if (!(d2 > 0.f) || jcol[nt][cj] <= irow[mt][ri]) dd = 0.f;
                        if (c & 1) ts1 += dd; else ts0 += dd;
                    }
        } else {
#pragma unroll
            for (int mt = 0; mt < 2; mt++)
#pragma unroll
                for (int nt = 0; nt < 8; nt++)
#pragma unroll
                    for (int c = 0; c < 4; c++) {
                        float d2 = nx[mt][c >> 1] + ny[nt][c & 1] - 2.f * acc[mt][nt][c];
                        float dd;
                        asm("sqrt.approx.f32 %0, %1;" : "=f"(dd) : "f"(d2));
                        if (!(d2 > 0.f)) dd = 0.f;
                        if (c & 1) ts1 += dd; else ts0 += dd;
                    }
        }
        float tsum = ts0 + ts1;
#pragma unroll
        for (int o = 16; o; o >>= 1) tsum += __shfl_xor_sync(0xffffffffu, tsum, o);
        if (lane == 0) g_partials[job * 8 + warp] = tsum;

        Jcur = Jnext;
    }
}

// ---------------------------------------------------------------------------
// Kernel 2: deterministic double-precision finalize (36864 warp partials).
// ---------------------------------------------------------------------------
__global__ void finalize_kernel(float* __restrict__ out) {
    __shared__ double sd[256];
    int tid = threadIdx.x;
    double s = 0.0;
    for (int i = tid; i < N_JOBS * 8; i += 256) {
        double v = (double)g_partials[i];
        s += (i < N_CROSS_CTAS * 8) ? v : -v;
    }
    sd[tid] = s;
    __syncthreads();
    for (int o = 128; o; o >>= 1) {
        if (tid < o) sd[tid] += sd[tid + o];
        __syncthreads();
    }
    if (tid == 0)
        out[0] = (float)(sd[0] / ((double)NB * NPTS * NPTS));
}

// ---------------------------------------------------------------------------
extern "C" void kernel_launch(void* const* d_in, const int* in_sizes, int n_in,
                              void* d_out, int out_size) {
    const float* X = (const float*)d_in[0];
    const float* Y = (const float*)d_in[1];

    cudaFuncSetAttribute(dist_kernel,
                         cudaFuncAttributeMaxDynamicSharedMemorySize, SMEM_REQ);

    prep_kernel<<<2048, 256>>>(X, Y);   // 8 rows/warp
    dist_kernel<<<N_CTAS, 256, SMEM_REQ>>>();
    finalize_kernel<<<1, 256>>>((float*)d_out);
}

// round 7
// speedup vs baseline: 1.0332x; 1.0332x over previous
#include <cuda_runtime.h>
#include <cuda_bf16.h>
#include <cuda_fp8.h>
#include <cstdint>

// Energy-distance loss, FP8 QMMA, pipelined with minimal carried state.
//   loss = mean_b[ mean||x-y|| - 0.5 mean||x-x'|| - 0.5 mean||y-y'|| ]
// R7: R6's prefetch retried WITHOUT register spills: no Job structs live
// across the mainloop; A/NX double-buffered by change-parity; B/NY by
// job parity; one barrier per job; per-warp global partials.

#define NPTS  512
#define DIMS  128
#define NB    128
#define NROWS 65536
#define N_CROSS_CTAS 2048
#define N_SELF_CTAS  1280
#define N_JOBS (N_CROSS_CTAS + 2 * N_SELF_CTAS)   // 4608
#define JOBS_PER_CTA 16
#define N_CTAS (N_JOBS / JOBS_PER_CTA)            // 288

__device__ uint8_t g_fx[NROWS * DIMS];
__device__ uint8_t g_fy[NROWS * DIMS];
__device__ float g_norm_x[NROWS];
__device__ float g_norm_y[NROWS];
__device__ float g_partials[N_JOBS * 8];

// smem layout (bytes from 1024-aligned base)
#define OFF_A    0        // A[pa] at pa*16384        (2 x 16 KB)
#define OFF_B    32768    // B[pb] at 32768+pb*16384  (2 x 16 KB)
#define OFF_NX   65536    // NX[pa] at +pa*512
#define OFF_NY   66560    // NY[pb] at +pb*512
#define SMEM_REQ (1024 + 67584)

__device__ __forceinline__ uint32_t smem_u32(const void* p) {
    uint32_t a;
    asm("{ .reg .u64 t; cvta.to.shared.u64 t, %1; cvt.u32.u64 %0, t; }"
        : "=r"(a) : "l"(p));
    return a;
}

// int-only decode for epilogue params (no pointers kept live)
__device__ __forceinline__ void decode_lite(int job, int& tr, int& tc, bool& selfm) {
    if (job < N_CROSS_CTAS) {
        int t = job & 15;
        tr = t >> 2; tc = t & 3;
        selfm = false;
    } else {
        int r = job - N_CROSS_CTAS;
        if (r >= N_SELF_CTAS) r -= N_SELF_CTAS;
        int t = r - (r / 10) * 10;
        int trr = 0;
        while (t >= 4 - trr) { t -= 4 - trr; trr++; }
        tr = trr; tc = trr + t;
        selfm = true;
    }
}

// full decode for staging (short-lived)
__device__ __forceinline__ void decode_ptrs(int job,
                                            const uint8_t*& Ab, const uint8_t*& Bb,
                                            const float*& nA, const float*& nB) {
    if (job < N_CROSS_CTAS) {
        int b = job >> 4;
        int t = job & 15;
        int tr = t >> 2, tc = t & 3;
        Ab = g_fx + ((size_t)b * NPTS + tr * 128) * DIMS;
        Bb = g_fy + ((size_t)b * NPTS + tc * 128) * DIMS;
        nA = g_norm_x + b * NPTS + tr * 128;
        nB = g_norm_y + b * NPTS + tc * 128;
    } else {
        int r = job - N_CROSS_CTAS;
        int isY = (r >= N_SELF_CTAS);
        if (isY) r -= N_SELF_CTAS;
        int b = r / 10;
        int t = r - b * 10;
        int trr = 0;
        while (t >= 4 - trr) { t -= 4 - trr; trr++; }
        int tr = trr, tc = trr + t;
        const uint8_t* base = isY ? g_fy : g_fx;
        const float* nbase = isY ? g_norm_y : g_norm_x;
        Ab = base + ((size_t)b * NPTS + tr * 128) * DIMS;
        Bb = base + ((size_t)b * NPTS + tc * 128) * DIMS;
        nA = nbase + b * NPTS + tr * 128;
        nB = nbase + b * NPTS + tc * 128;
    }
}

// ---------------------------------------------------------------------------
// Kernel 0: fp32 -> e4m3 convert + exact fp32 squared norms. 8 rows/warp.
// ---------------------------------------------------------------------------
__global__ void prep_kernel(const float* __restrict__ X,
                            const float* __restrict__ Y) {
    int warp = (blockIdx.x * blockDim.x + threadIdx.x) >> 5;
    int lane = threadIdx.x & 31;
    int row8 = warp * 8;
    const float* src; uint8_t* dst; float* ndst; int r0;
    if (row8 < NROWS) { src = X; dst = g_fx; ndst = g_norm_x; r0 = row8; }
    else              { src = Y; dst = g_fy; ndst = g_norm_y; r0 = row8 - NROWS; }

    float4 v[8];
    float s[8];
#pragma unroll
    for (int k = 0; k < 8; k++) {
        v[k] = ((const float4*)(src + (size_t)(r0 + k) * DIMS))[lane];
        s[k] = v[k].x * v[k].x + v[k].y * v[k].y + v[k].z * v[k].z + v[k].w * v[k].w;
    }
#pragma unroll
    for (int k = 0; k < 8; k++) {
        float2 lo = make_float2(v[k].x, v[k].y);
        float2 hi = make_float2(v[k].z, v[k].w);
        unsigned p0 = __nv_cvt_float2_to_fp8x2(lo, __NV_SATFINITE, __NV_E4M3);
        unsigned p1 = __nv_cvt_float2_to_fp8x2(hi, __NV_SATFINITE, __NV_E4M3);
        *(unsigned*)(dst + (size_t)(r0 + k) * DIMS + lane * 4) =
            (p0 & 0xffffu) | (p1 << 16);
#pragma unroll
        for (int o = 16; o; o >>= 1) s[k] += __shfl_xor_sync(0xffffffffu, s[k], o);
        if (lane == 0) ndst[r0 + k] = s[k];
    }
}

// ---------------------------------------------------------------------------
// staging helpers (all state dies before the mainloop)
// ---------------------------------------------------------------------------
__device__ __forceinline__ void stage_B(const uint8_t* Bb, const float* nB,
                                        uint32_t sbase, int pb, int tid) {
    uint32_t dstB = sbase + OFF_B + pb * 16384;
#pragma unroll
    for (int q = 0; q < 4; q++) {
        int idx = tid + q * 256;
        int r = idx >> 3, u = idx & 7;
        int soff = r * 128 + ((u ^ (r & 7)) << 4);
        asm volatile("cp.async.cg.shared.global [%0], [%1], 16;"
                     :: "r"(dstB + soff),
                        "l"((const void*)(Bb + (size_t)r * DIMS + u * 16)));
    }
    if (tid < 32)
        asm volatile("cp.async.ca.shared.global [%0], [%1], 16;"
                     :: "r"(sbase + OFF_NY + pb * 512 + tid * 16),
                        "l"((const void*)(nB + tid * 4)));
}

__device__ __forceinline__ void stage_A(const uint8_t* Ab, const float* nA,
                                        uint32_t sbase, int pa, int tid) {
    uint32_t dstA = sbase + OFF_A + pa * 16384;
#pragma unroll
    for (int q = 0; q < 4; q++) {
        int idx = tid + q * 256;
        int r = idx >> 3, u = idx & 7;
        int soff = r * 128 + ((u ^ (r & 7)) << 4);
        asm volatile("cp.async.cg.shared.global [%0], [%1], 16;"
                     :: "r"(dstA + soff),
                        "l"((const void*)(Ab + (size_t)r * DIMS + u * 16)));
    }
    if (tid >= 32 && tid < 64)
        asm volatile("cp.async.ca.shared.global [%0], [%1], 16;"
                     :: "r"(sbase + OFF_NX + pa * 512 + (tid - 32) * 16),
                        "l"((const void*)(nA + (tid - 32) * 4)));
}

// ---------------------------------------------------------------------------
// Kernel 1: pipelined 128x128 fp8 distance tiles, minimal carried state.
// ---------------------------------------------------------------------------
__global__ __launch_bounds__(256, 2)
void dist_kernel() {
    extern __shared__ char dyn_smem[];
    char* sm = (char*)((((uintptr_t)dyn_smem) + 1023) & ~(uintptr_t)1023);
    uint32_t sbase = smem_u32(sm);

    int tid  = threadIdx.x;
    int lane = tid & 31;
    int warp = tid >> 5;
    int wm   = warp >> 1;
    int wn   = warp & 1;

    int a_r = (lane & 7) + ((lane >> 3) & 1) * 8;
    int a_u = lane >> 4;
    int b_r = (lane & 7) + ((lane >> 4) << 3);
    int b_u = (lane >> 3) & 1;

    int j0 = blockIdx.x * JOBS_PER_CTA;
    int j1 = j0 + JOBS_PER_CTA;

    // carried pipeline state (tiny)
    const uint8_t* curAb;      // A pointer of current job
    int pa = 0;                // A-buffer parity of current job
    int pa_next = 0;
    const uint8_t* nextAb;

    // prologue: stage job j0
    {
        const uint8_t *Ab, *Bb; const float *nA, *nB;
        decode_ptrs(j0, Ab, Bb, nA, nB);
        stage_B(Bb, nB, sbase, 0, tid);
        stage_A(Ab, nA, sbase, 0, tid);
        asm volatile("cp.async.commit_group;");
        curAb = Ab;
        nextAb = Ab;
    }

    for (int job = j0; job < j1; job++) {
        int pb = job & 1;

        asm volatile("cp.async.wait_group 0;" ::: "memory");
        __syncthreads();

        // ---- prefetch job+1 (state dies here) ----
        if (job + 1 < j1) {
            const uint8_t *Ab, *Bb; const float *nA, *nB;
            decode_ptrs(job + 1, Ab, Bb, nA, nB);
            stage_B(Bb, nB, sbase, pb ^ 1, tid);
            if (Ab != curAb) {
                pa_next = pa ^ 1;
                stage_A(Ab, nA, sbase, pa_next, tid);
            } else {
                pa_next = pa;
            }
            nextAb = Ab;
            asm volatile("cp.async.commit_group;");
        }

        // ---- mainloop ----
        uint32_t sA = sbase + OFF_A + pa * 16384;
        uint32_t sB = sbase + OFF_B + pb * 16384;

        float acc[2][8][4];
#pragma unroll
        for (int mt = 0; mt < 2; mt++)
#pragma unroll
            for (int nt = 0; nt < 8; nt++)
#pragma unroll
                for (int c = 0; c < 4; c++) acc[mt][nt][c] = 0.f;

#pragma unroll
        for (int kk = 0; kk < 4; kk++) {
            unsigned af[2][4];
#pragma unroll
            for (int mt = 0; mt < 2; mt++) {
                int r = wm * 32 + mt * 16 + a_r;
                int u = kk * 2 + a_u;
                unsigned addr = sA + (unsigned)(r * 128 + ((u ^ (r & 7)) << 4));
                asm volatile(
                    "ldmatrix.sync.aligned.m8n8.x4.shared.b16 {%0,%1,%2,%3}, [%4];"
                    : "=r"(af[mt][0]), "=r"(af[mt][1]), "=r"(af[mt][2]), "=r"(af[mt][3])
                    : "r"(addr));
            }
#pragma unroll
            for (int pp = 0; pp < 4; pp++) {
                int r = wn * 64 + pp * 16 + b_r;
                int u = kk * 2 + b_u;
                unsigned addr = sB + (unsigned)(r * 128 + ((u ^ (r & 7)) << 4));
                unsigned bf[4];
                asm volatile(
                    "ldmatrix.sync.aligned.m8n8.x4.shared.b16 {%0,%1,%2,%3}, [%4];"
                    : "=r"(bf[0]), "=r"(bf[1]), "=r"(bf[2]), "=r"(bf[3])
                    : "r"(addr));
#pragma unroll
                for (int mt = 0; mt < 2; mt++) {
                    asm volatile(
                        "mma.sync.aligned.m16n8k32.row.col.f32.e4m3.e4m3.f32 "
                        "{%0,%1,%2,%3}, {%4,%5,%6,%7}, {%8,%9}, {%0,%1,%2,%3};"
                        : "+f"(acc[mt][2*pp][0]), "+f"(acc[mt][2*pp][1]),
                          "+f"(acc[mt][2*pp][2]), "+f"(acc[mt][2*pp][3])
                        : "r"(af[mt][0]), "r"(af[mt][1]), "r"(af[mt][2]), "r"(af[mt][3]),
                          "r"(bf[0]), "r"(bf[1]));
                    asm volatile(
                        "mma.sync.aligned.m16n8k32.row.col.f32.e4m3.e4m3.f32 "
                        "{%0,%1,%2,%3}, {%4,%5,%6,%7}, {%8,%9}, {%0,%1,%2,%3};"
                        : "+f"(acc[mt][2*pp+1][0]), "+f"(acc[mt][2*pp+1][1]),
                          "+f"(acc[mt][2*pp+1][2]), "+f"(acc[mt][2*pp+1][3])
                        : "r"(af[mt][0]), "r"(af[mt][1]), "r"(af[mt][2]), "r"(af[mt][3]),
                          "r"(bf[2]), "r"(bf[3]));
                }
            }
        }

        // ---- epilogue (params recomputed, no pointers) ----
        int tr, tc; bool selfm;
        decode_lite(job, tr, tc, selfm);
        bool diag = selfm && (tr == tc);

        const char* NXp = sm + OFF_NX + pa * 512;
        const char* NYp = sm + OFF_NY + pb * 512;
        int g  = lane >> 2;
        int ct = lane & 3;

        float nx[2][2];
#pragma unroll
        for (int mt = 0; mt < 2; mt++) {
            int r0 = wm * 32 + mt * 16 + g;
            nx[mt][0] = *(const float*)(NXp + r0 * 4);
            nx[mt][1] = *(const float*)(NXp + (r0 + 8) * 4);
        }
        float ny[8][2];
#pragma unroll
        for (int nt = 0; nt < 8; nt++) {
            int c0 = wn * 64 + nt * 8 + 2 * ct;
            ny[nt][0] = *(const float*)(NYp + c0 * 4);
            ny[nt][1] = *(const float*)(NYp + (c0 + 1) * 4);
        }

        float ts0 = 0.f, ts1 = 0.f;
        if (diag) {
#pragma unroll
            for (int mt = 0; mt < 2; mt++)
#pragma unroll
                for (int nt = 0; nt < 8; nt++)
#pragma unroll
                    for (int c = 0; c < 4; c++) {
                        int ri = c >> 1, cj = c & 1;
                        int irow = wm * 32 + mt * 16 + g + ri * 8;          // local
                        int jcol = wn * 64 + nt * 8 + 2 * ct + cj;          // local
                        float d2 = fmaf(acc[mt][nt][c], -2.f, nx[mt][ri]) + ny[nt][cj];
                        d2 = fmaxf(d2, 0.f);
                        float dd;
                        asm("sqrt.approx.f32 %0, %1;" : "=f"(dd) : "f"(d2));
                        if (jcol <= irow) dd = 0.f;    // tr==tc: local compare ok
                        if (c & 1) ts1 += dd; else ts0 += dd;
                    }
        } else {
#pragma unroll
            for (int mt = 0; mt < 2; mt++)
#pragma unroll
                for (int nt = 0; nt < 8; nt++)
#pragma unroll
                    for (int c = 0; c < 4; c++) {
                        float d2 = fmaf(acc[mt][nt][c], -2.f, nx[mt][c >> 1]) + ny[nt][c & 1];
                        d2 = fmaxf(d2, 0.f);
                        float dd;
                        asm("sqrt.approx.f32 %0, %1;" : "=f"(dd) : "f"(d2));
                        if (c & 1) ts1 += dd; else ts0 += dd;
                    }
        }
        float tsum = ts0 + ts1;
#pragma unroll
        for (int o = 16; o; o >>= 1) tsum += __shfl_xor_sync(0xffffffffu, tsum, o);
        if (lane == 0) g_partials[job * 8 + warp] = tsum;

        pa = pa_next;
        curAb = nextAb;
    }
}

// ---------------------------------------------------------------------------
// Kernel 2: deterministic double-precision finalize.
// ---------------------------------------------------------------------------
__global__ void finalize_kernel(float* __restrict__ out) {
    __shared__ double sd[256];
    int tid = threadIdx.x;
    double s = 0.0;
    for (int i = tid; i < N_JOBS * 8; i += 256) {
        double v = (double)g_partials[i];
        s += (i < N_CROSS_CTAS * 8) ? v : -v;
    }
    sd[tid] = s;
    __syncthreads();
    for (int o = 128; o; o >>= 1) {
        if (tid < o) sd[tid] += sd[tid + o];
        __syncthreads();
    }
    if (tid == 0)
        out[0] = (float)(sd[0] / ((double)NB * NPTS * NPTS));
}

// ---------------------------------------------------------------------------
extern "C" void kernel_launch(void* const* d_in, const int* in_sizes, int n_in,
                              void* d_out, int out_size) {
    const float* X = (const float*)d_in[0];
    const float* Y = (const float*)d_in[1];

    cudaFuncSetAttribute(dist_kernel,
                         cudaFuncAttributeMaxDynamicSharedMemorySize, SMEM_REQ);

    prep_kernel<<<2048, 256>>>(X, Y);
    dist_kernel<<<N_CTAS, 256, SMEM_REQ>>>();
    finalize_kernel<<<1, 256>>>((float*)d_out);
}

// round 8
// speedup vs baseline: 1.0506x; 1.0169x over previous
#include <cuda_runtime.h>
#include <cuda_bf16.h>
#include <cuda_fp16.h>
#include <cuda_fp8.h>
#include <cstdint>

// Energy-distance loss, FP8 QMMA with FP16 accumulators (2x legacy rate).
//   loss = mean_b[ mean||x-y|| - 0.5 mean||x-x'|| - 0.5 mean||y-y'|| ]
// Evidence R2/R4/R5: dist kernel is tensor-pipe bound at a dtype-independent
// ~512 MAC/cyc/SM with f32 accum; f16 accum doubles the rate. e4m3 products
// are exact in fp16; only K=128 accumulation rounds (zero-mean, cancels
// between cross and self terms like the fp8 quantization noise did).

#define NPTS  512
#define DIMS  128
#define NB    128
#define NROWS 65536
#define N_CROSS_CTAS 2048
#define N_SELF_CTAS  1280
#define N_JOBS (N_CROSS_CTAS + 2 * N_SELF_CTAS)   // 4608
#define JOBS_PER_CTA 16
#define N_CTAS (N_JOBS / JOBS_PER_CTA)            // 288

__device__ uint8_t g_fx[NROWS * DIMS];
__device__ uint8_t g_fy[NROWS * DIMS];
__device__ float g_norm_x[NROWS];
__device__ float g_norm_y[NROWS];
__device__ float g_partials[N_JOBS * 8];

// smem layout (bytes from 1024-aligned base)
#define OFF_A    0        // 16 KB fp8 tile, 128B rows, xor-swizzled
#define OFF_B    16384    // 16 KB
#define OFF_NX   32768    // 512 B
#define OFF_NY   33280    // 512 B
#define SMEM_REQ (1024 + 33824)

__device__ __forceinline__ uint32_t smem_u32(const void* p) {
    uint32_t a;
    asm("{ .reg .u64 t; cvta.to.shared.u64 t, %1; cvt.u32.u64 %0, t; }"
        : "=r"(a) : "l"(p));
    return a;
}

// ---------------------------------------------------------------------------
// Kernel 0: fp32 -> e4m3 convert + exact fp32 squared norms. 8 rows/warp.
// ---------------------------------------------------------------------------
__global__ void prep_kernel(const float* __restrict__ X,
                            const float* __restrict__ Y) {
    int warp = (blockIdx.x * blockDim.x + threadIdx.x) >> 5;
    int lane = threadIdx.x & 31;
    int row8 = warp * 8;
    const float* src; uint8_t* dst; float* ndst; int r0;
    if (row8 < NROWS) { src = X; dst = g_fx; ndst = g_norm_x; r0 = row8; }
    else              { src = Y; dst = g_fy; ndst = g_norm_y; r0 = row8 - NROWS; }

    float4 v[8];
    float s[8];
#pragma unroll
    for (int k = 0; k < 8; k++) {
        v[k] = ((const float4*)(src + (size_t)(r0 + k) * DIMS))[lane];
        s[k] = v[k].x * v[k].x + v[k].y * v[k].y + v[k].z * v[k].z + v[k].w * v[k].w;
    }
#pragma unroll
    for (int k = 0; k < 8; k++) {
        float2 lo = make_float2(v[k].x, v[k].y);
        float2 hi = make_float2(v[k].z, v[k].w);
        unsigned p0 = __nv_cvt_float2_to_fp8x2(lo, __NV_SATFINITE, __NV_E4M3);
        unsigned p1 = __nv_cvt_float2_to_fp8x2(hi, __NV_SATFINITE, __NV_E4M3);
        *(unsigned*)(dst + (size_t)(r0 + k) * DIMS + lane * 4) =
            (p0 & 0xffffu) | (p1 << 16);
#pragma unroll
        for (int o = 16; o; o >>= 1) s[k] += __shfl_xor_sync(0xffffffffu, s[k], o);
        if (lane == 0) ndst[r0 + k] = s[k];
    }
}

// ---------------------------------------------------------------------------
// Kernel 1: 128x128 distance tiles, e4m3 x e4m3 -> f16 accum QMMA.
// 8 warps in 4(m) x 2(n); warp tile 32x64 = 2 x 8 (m16n8) x 4 k32 chunks.
// ---------------------------------------------------------------------------
__global__ __launch_bounds__(256, 2)
void dist_kernel() {
    extern __shared__ char dyn_smem[];
    char* sm = (char*)((((uintptr_t)dyn_smem) + 1023) & ~(uintptr_t)1023);
    uint32_t sbase = smem_u32(sm);

    int tid  = threadIdx.x;
    int lane = tid & 31;
    int warp = tid >> 5;
    int wm   = warp >> 1;
    int wn   = warp & 1;

    int a_r = (lane & 7) + ((lane >> 3) & 1) * 8;
    int a_u = lane >> 4;
    int b_r = (lane & 7) + ((lane >> 4) << 3);
    int b_u = (lane >> 3) & 1;

    int j0 = blockIdx.x * JOBS_PER_CTA;
    int j1 = j0 + JOBS_PER_CTA;

    const uint8_t* prevAbase = (const uint8_t*)0;

    for (int job = j0; job < j1; job++) {
        // ---- job decode ----
        const uint8_t *Ap, *Bp;
        const float *nAp, *nBp;
        int b, tr, tc;
        bool selfm;
        if (job < N_CROSS_CTAS) {
            b = job >> 4;
            int t = job & 15;
            tr = t >> 2; tc = t & 3;
            Ap = g_fx; Bp = g_fy; nAp = g_norm_x; nBp = g_norm_y;
            selfm = false;
        } else {
            int r = job - N_CROSS_CTAS;
            int isY = (r >= N_SELF_CTAS);
            if (isY) r -= N_SELF_CTAS;
            b = r / 10;
            int t = r - b * 10;
            int trr = 0, tt = t;
            while (tt >= 4 - trr) { tt -= 4 - trr; trr++; }
            tr = trr; tc = trr + tt;
            Ap = isY ? g_fy : g_fx;
            Bp = Ap;
            nAp = isY ? g_norm_y : g_norm_x;
            nBp = nAp;
            selfm = true;
        }
        bool diag = selfm && (tr == tc);
        const uint8_t* Abase = Ap + ((size_t)b * NPTS + tr * 128) * DIMS;
        const uint8_t* Bbase = Bp + ((size_t)b * NPTS + tc * 128) * DIMS;
        bool reuseA = (Abase == prevAbase);
        prevAbase = Abase;

        __syncthreads();   // prior job fully done with smem

        // ---- stage via cp.async ----
#pragma unroll
        for (int q = 0; q < 4; q++) {
            int idx = tid + q * 256;
            int r = idx >> 3, u = idx & 7;
            int soff = r * 128 + ((u ^ (r & 7)) << 4);
            asm volatile("cp.async.cg.shared.global [%0], [%1], 16;"
                         :: "r"(sbase + OFF_B + soff),
                            "l"((const void*)(Bbase + (size_t)r * DIMS + u * 16)));
            if (!reuseA)
                asm volatile("cp.async.cg.shared.global [%0], [%1], 16;"
                             :: "r"(sbase + OFF_A + soff),
                                "l"((const void*)(Abase + (size_t)r * DIMS + u * 16)));
        }
        if (tid < 128) {
            if (!reuseA)
                *(float*)(sm + OFF_NX + tid * 4) = nAp[b * NPTS + tr * 128 + tid];
        } else {
            *(float*)(sm + OFF_NY + (tid - 128) * 4) = nBp[b * NPTS + tc * 128 + tid - 128];
        }
        asm volatile("cp.async.commit_group;");
        asm volatile("cp.async.wait_group 0;" ::: "memory");
        __syncthreads();

        // ---- mainloop: 4 k32 chunks, f16 accumulators ----
        // acc[mt][nt][0] = packed {row g, cols 2ct,2ct+1}
        // acc[mt][nt][1] = packed {row g+8, cols 2ct,2ct+1}
        unsigned acc[2][8][2];
#pragma unroll
        for (int mt = 0; mt < 2; mt++)
#pragma unroll
            for (int nt = 0; nt < 8; nt++) {
                acc[mt][nt][0] = 0u;
                acc[mt][nt][1] = 0u;
            }

        uint32_t sA = sbase + OFF_A;
        uint32_t sB = sbase + OFF_B;

#pragma unroll
        for (int kk = 0; kk < 4; kk++) {
            unsigned af[2][4];
#pragma unroll
            for (int mt = 0; mt < 2; mt++) {
                int r = wm * 32 + mt * 16 + a_r;
                int u = kk * 2 + a_u;
                unsigned addr = sA + (unsigned)(r * 128 + ((u ^ (r & 7)) << 4));
                asm volatile(
                    "ldmatrix.sync.aligned.m8n8.x4.shared.b16 {%0,%1,%2,%3}, [%4];"
                    : "=r"(af[mt][0]), "=r"(af[mt][1]), "=r"(af[mt][2]), "=r"(af[mt][3])
                    : "r"(addr));
            }
#pragma unroll
            for (int pp = 0; pp < 4; pp++) {
                int r = wn * 64 + pp * 16 + b_r;
                int u = kk * 2 + b_u;
                unsigned addr = sB + (unsigned)(r * 128 + ((u ^ (r & 7)) << 4));
                unsigned bf[4];
                asm volatile(
                    "ldmatrix.sync.aligned.m8n8.x4.shared.b16 {%0,%1,%2,%3}, [%4];"
                    : "=r"(bf[0]), "=r"(bf[1]), "=r"(bf[2]), "=r"(bf[3])
                    : "r"(addr));
#pragma unroll
                for (int mt = 0; mt < 2; mt++) {
                    asm volatile(
                        "mma.sync.aligned.m16n8k32.row.col.f16.e4m3.e4m3.f16 "
                        "{%0,%1}, {%2,%3,%4,%5}, {%6,%7}, {%0,%1};"
                        : "+r"(acc[mt][2*pp][0]), "+r"(acc[mt][2*pp][1])
                        : "r"(af[mt][0]), "r"(af[mt][1]), "r"(af[mt][2]), "r"(af[mt][3]),
                          "r"(bf[0]), "r"(bf[1]));
                    asm volatile(
                        "mma.sync.aligned.m16n8k32.row.col.f16.e4m3.e4m3.f16 "
                        "{%0,%1}, {%2,%3,%4,%5}, {%6,%7}, {%0,%1};"
                        : "+r"(acc[mt][2*pp+1][0]), "+r"(acc[mt][2*pp+1][1])
                        : "r"(af[mt][0]), "r"(af[mt][1]), "r"(af[mt][2]), "r"(af[mt][3]),
                          "r"(bf[2]), "r"(bf[3]));
                }
            }
        }

        // ---- epilogue ----
        int g  = lane >> 2;
        int ct = lane & 3;

        float nx[2][2];
#pragma unroll
        for (int mt = 0; mt < 2; mt++) {
            int r0 = wm * 32 + mt * 16 + g;
            nx[mt][0] = *(const float*)(sm + OFF_NX + r0 * 4);
            nx[mt][1] = *(const float*)(sm + OFF_NX + (r0 + 8) * 4);
        }
        float ny[8][2];
#pragma unroll
        for (int nt = 0; nt < 8; nt++) {
            int c0 = wn * 64 + nt * 8 + 2 * ct;
            ny[nt][0] = *(const float*)(sm + OFF_NY + c0 * 4);
            ny[nt][1] = *(const float*)(sm + OFF_NY + (c0 + 1) * 4);
        }

        float ts0 = 0.f, ts1 = 0.f;
        if (diag) {
#pragma unroll
            for (int mt = 0; mt < 2; mt++)
#pragma unroll
                for (int nt = 0; nt < 8; nt++)
#pragma unroll
                    for (int ri = 0; ri < 2; ri++) {
                        float2 dot = __half22float2(
                            *(const __half2*)&acc[mt][nt][ri]);
                        int irow = wm * 32 + mt * 16 + g + ri * 8;
                        int jc0  = wn * 64 + nt * 8 + 2 * ct;
                        float d2a = fmaf(dot.x, -2.f, nx[mt][ri]) + ny[nt][0];
                        float d2b = fmaf(dot.y, -2.f, nx[mt][ri]) + ny[nt][1];
                        d2a = fmaxf(d2a, 0.f);
                        d2b = fmaxf(d2b, 0.f);
                        float da, db;
                        asm("sqrt.approx.f32 %0, %1;" : "=f"(da) : "f"(d2a));
                        asm("sqrt.approx.f32 %0, %1;" : "=f"(db) : "f"(d2b));
                        if (jc0 <= irow)     da = 0.f;
                        if (jc0 + 1 <= irow) db = 0.f;
                        ts0 += da; ts1 += db;
                    }
        } else {
#pragma unroll
            for (int mt = 0; mt < 2; mt++)
#pragma unroll
                for (int nt = 0; nt < 8; nt++)
#pragma unroll
                    for (int ri = 0; ri < 2; ri++) {
                        float2 dot = __half22float2(
                            *(const __half2*)&acc[mt][nt][ri]);
                        float d2a = fmaf(dot.x, -2.f, nx[mt][ri]) + ny[nt][0];
                        float d2b = fmaf(dot.y, -2.f, nx[mt][ri]) + ny[nt][1];
                        d2a = fmaxf(d2a, 0.f);
                        d2b = fmaxf(d2b, 0.f);
                        float da, db;
                        asm("sqrt.approx.f32 %0, %1;" : "=f"(da) : "f"(d2a));
                        asm("sqrt.approx.f32 %0, %1;" : "=f"(db) : "f"(d2b));
                        ts0 += da; ts1 += db;
                    }
        }
        float tsum = ts0 + ts1;
#pragma unroll
        for (int o = 16; o; o >>= 1) tsum += __shfl_xor_sync(0xffffffffu, tsum, o);
        if (lane == 0) g_partials[job * 8 + warp] = tsum;
    }
}

// ---------------------------------------------------------------------------
// Kernel 2: deterministic double-precision finalize.
// ---------------------------------------------------------------------------
__global__ void finalize_kernel(float* __restrict__ out) {
    __shared__ double sd[256];
    int tid = threadIdx.x;
    double s = 0.0;
    for (int i = tid; i < N_JOBS * 8; i += 256) {
        double v = (double)g_partials[i];
        s += (i < N_CROSS_CTAS * 8) ? v : -v;
    }
    sd[tid] = s;
    __syncthreads();
    for (int o = 128; o; o >>= 1) {
        if (tid < o) sd[tid] += sd[tid + o];
        __syncthreads();
    }
    if (tid == 0)
        out[0] = (float)(sd[0] / ((double)NB * NPTS * NPTS));
}

// ---------------------------------------------------------------------------
extern "C" void kernel_launch(void* const* d_in, const int* in_sizes, int n_in,
                              void* d_out, int out_size) {
    const float* X = (const float*)d_in[0];
    const float* Y = (const float*)d_in[1];

    cudaFuncSetAttribute(dist_kernel,
                         cudaFuncAttributeMaxDynamicSharedMemorySize, SMEM_REQ);

    prep_kernel<<<2048, 256>>>(X, Y);
    dist_kernel<<<N_CTAS, 256, SMEM_REQ>>>();
    finalize_kernel<<<1, 256>>>((float*)d_out);
}